// round 11
// baseline (speedup 1.0000x reference)
#include <cuda_runtime.h>
#include <cstdint>
#include <cstddef>

#define T_STEPS 2048
#define B_SIZE  256
#define I_SIZE  64
#define H_SIZE  128

// Scratch: input projections x@Wi + bi, layout [T][B][3*H] (805 MB)
__device__ float g_xproj[(size_t)T_STEPS * B_SIZE * 3 * H_SIZE];
// Scratch: hidden states hs [T][B][H] (268 MB) for deferred classifier
__device__ float g_hs[(size_t)T_STEPS * B_SIZE * H_SIZE];

__device__ __forceinline__ float sigmoidf_(float x) {
    return 1.0f / (1.0f + __expf(-x));
}
__device__ __forceinline__ float tanhf_(float x) {
    return 1.0f - 2.0f / (1.0f + __expf(2.0f * x));
}

// ---- packed f32x2 helpers (Blackwell FFMA2) --------------------------------
__device__ __forceinline__ unsigned long long fma2_(unsigned long long a,
                                                    unsigned long long b,
                                                    unsigned long long c) {
    unsigned long long d;
    asm("fma.rn.f32x2 %0, %1, %2, %3;" : "=l"(d) : "l"(a), "l"(b), "l"(c));
    return d;
}
__device__ __forceinline__ unsigned long long dup2_(float x) {
    unsigned long long d;
    asm("mov.b64 %0, {%1, %1};" : "=l"(d) : "f"(x));
    return d;
}
__device__ __forceinline__ float2 unpack2_(unsigned long long v) {
    float2 r;
    asm("mov.b64 {%0, %1}, %2;" : "=f"(r.x), "=f"(r.y) : "l"(v));
    return r;
}

// ============================================================================
// Phase 1 (persistent): xproj[t,b, g*128+j] = sum_i x[t,b,i]*Wg[i,j] + bg[j]
// grid = 576 blocks (192 per gate), 128 threads, 4 blocks/SM (16 warps).
// Each block loads its gate's W [64x128] into SMEM ONCE, then loops over
// ~43 x-tiles of 64 rows. Inner compute identical to the R10 kernel:
// 4x16 register tile, FFMA2-packed over cols, XOR-swizzled x tile.
// SMEM exactly 48KB: xs 16KB + ws 32KB -> 4 blocks/SM = 192KB.
// ============================================================================
#define XP_BLOCKS_PER_GATE 192
#define XP_TILES_PER_GATE  ((T_STEPS * B_SIZE) / 64)   // 8192

// swizzled transposed x tile: element (i, row) at xs[i*64 + (row ^ (i & 60))]
#define XS_IDX(i, row) ((i) * 64 + ((row) ^ ((i) & 60)))

__global__ __launch_bounds__(128, 4) void xproj_kernel(
    const float* __restrict__ x,
    const float* __restrict__ Wir, const float* __restrict__ Wiz, const float* __restrict__ Win,
    const float* __restrict__ bir, const float* __restrict__ biz, const float* __restrict__ bin_)
{
    __shared__ __align__(16) float xs[I_SIZE * 64];       // 16384 B
    __shared__ __align__(16) float ws[I_SIZE * H_SIZE];   // 32768 B

    const int g    = blockIdx.x / XP_BLOCKS_PER_GATE;     // 0..2
    const int slot = blockIdx.x % XP_BLOCKS_PER_GATE;

    const float* __restrict__ W    = (g == 0) ? Wir : (g == 1) ? Wiz : Win;
    const float* __restrict__ bias = (g == 0) ? bir : (g == 1) ? biz : bin_;

    const int tid = threadIdx.x;

    // Load W [64 x 128] once per block.
    const float4* __restrict__ Wg4 = (const float4*)W;
    #pragma unroll
    for (int s = 0; s < 16; s++) {
        int idx4 = tid + 128 * s;            // 0..2047
        ((float4*)ws)[idx4] = Wg4[idx4];
    }

    const int tr = tid & 15;                 // 16 row-groups
    const int tc = tid >> 4;                 // 8 col-groups
    const int r0 = tr * 4;
    const int c0 = tc * 16;

    for (int tile = slot; tile < XP_TILES_PER_GATE; tile += XP_BLOCKS_PER_GATE) {
        const size_t r_base = (size_t)tile * 64;

        __syncthreads();   // previous iteration's readers done before xs overwrite
                           // (first iteration: makes ws visible too)

        // Load x tile [64 rows x 64 i] -> transposed+swizzled SMEM.
        const float4* __restrict__ xg4 = (const float4*)(x + r_base * I_SIZE);
        #pragma unroll
        for (int s = 0; s < 8; s++) {
            int idx4 = tid + 128 * s;        // 0..1023 float4s
            float4 v = xg4[idx4];
            int row = idx4 >> 4;             // 16 float4 per row
            int i0  = (idx4 & 15) * 4;
            xs[XS_IDX(i0 + 0, row)] = v.x;
            xs[XS_IDX(i0 + 1, row)] = v.y;
            xs[XS_IDX(i0 + 2, row)] = v.z;
            xs[XS_IDX(i0 + 3, row)] = v.w;
        }
        __syncthreads();

        unsigned long long accp[4][8];
        #pragma unroll
        for (int r = 0; r < 4; r++)
            #pragma unroll
            for (int c = 0; c < 8; c++)
                accp[r][c] = 0ull;

        #pragma unroll 4
        for (int k = 0; k < I_SIZE; k++) {
            float4 xa = *(const float4*)&xs[XS_IDX(k, r0)];
            const ulonglong2* wr = (const ulonglong2*)&ws[k * H_SIZE + c0];
            ulonglong2 wq0 = wr[0], wq1 = wr[1], wq2 = wr[2], wq3 = wr[3];
            unsigned long long wp[8] = {wq0.x, wq0.y, wq1.x, wq1.y,
                                        wq2.x, wq2.y, wq3.x, wq3.y};
            unsigned long long xd[4] = {dup2_(xa.x), dup2_(xa.y), dup2_(xa.z), dup2_(xa.w)};
            #pragma unroll
            for (int r = 0; r < 4; r++)
                #pragma unroll
                for (int c = 0; c < 8; c++)
                    accp[r][c] = fma2_(xd[r], wp[c], accp[r][c]);
        }

        // Bias (L1-cached global read).
        const float4* __restrict__ bp = (const float4*)(bias + c0);
        float4 b0 = bp[0], b1 = bp[1], b2 = bp[2], b3 = bp[3];
        float bv[16] = {b0.x, b0.y, b0.z, b0.w, b1.x, b1.y, b1.z, b1.w,
                        b2.x, b2.y, b2.z, b2.w, b3.x, b3.y, b3.z, b3.w};

        #pragma unroll
        for (int r = 0; r < 4; r++) {
            size_t row = r_base + (size_t)(r0 + r);
            float* op = g_xproj + row * (3 * H_SIZE) + g * H_SIZE + c0;
            #pragma unroll
            for (int q = 0; q < 4; q++) {
                float2 pa = unpack2_(accp[r][2 * q + 0]);
                float2 pb = unpack2_(accp[r][2 * q + 1]);
                float4 o;
                o.x = pa.x + bv[4 * q + 0];
                o.y = pa.y + bv[4 * q + 1];
                o.z = pb.x + bv[4 * q + 2];
                o.w = pb.y + bv[4 * q + 3];
                *(float4*)(op + 4 * q) = o;
            }
        }
    }
}

// ============================================================================
// Phase 2: persistent per-batch GRU recurrence (unchanged from R10).
// grid = 128 blocks (2 batch rows each), 384 threads.
// Epilogue parallelized: gate-2 updates row 0, gate-1 updates row 1.
// Classifier deferred to phase 3 (h written to g_hs); x(t+1) prefetched.
// ============================================================================
__global__ __launch_bounds__(384, 1) void gru_kernel(
    const float* __restrict__ Whr, const float* __restrict__ Whz, const float* __restrict__ Whn,
    const float* __restrict__ bhn)
{
    __shared__ __align__(16) float h_s[2][H_SIZE];
    __shared__ float r_s[2][H_SIZE];
    __shared__ float z0_s[H_SIZE];     // z row 0 (gate-1 keeps z1 in reg)
    __shared__ float a1_s[H_SIZE];     // n-dot row 1 (gate-2 keeps acc0)
    __shared__ float xn1_s[H_SIZE];    // xn row 1

    const int tid = threadIdx.x;
    const int g   = tid >> 7;       // 0=r, 1=z, 2=n
    const int j   = tid & 127;
    const int b0  = blockIdx.x * 2;

    const float* __restrict__ Wh = (g == 0) ? Whr : (g == 1) ? Whz : Whn;

    // Register-resident weight column: w[k] = Wh[k][j]
    float w[H_SIZE];
    #pragma unroll
    for (int k = 0; k < H_SIZE; k++) w[k] = Wh[k * H_SIZE + j];

    const float bhn_j = bhn[j];

    if (tid < 2 * H_SIZE) ((float*)h_s)[tid] = 0.0f;   // h0 = 0
    __syncthreads();

    const float* __restrict__ xp = g_xproj + (size_t)b0 * (3 * H_SIZE) + g * H_SIZE + j;
    const size_t step_stride = (size_t)B_SIZE * 3 * H_SIZE;

    float x0 = xp[0];
    float x1 = xp[3 * H_SIZE];

    for (int t = 0; t < T_STEPS; t++) {
        float nx0 = 0.0f, nx1 = 0.0f;
        if (t + 1 < T_STEPS) {
            const float* xq = xp + (size_t)(t + 1) * step_stride;
            nx0 = xq[0];
            nx1 = xq[3 * H_SIZE];
        }

        float a0 = 0.f, a1 = 0.f, a2 = 0.f, a3 = 0.f;
        float d0 = 0.f, d1 = 0.f, d2 = 0.f, d3 = 0.f;
        #pragma unroll
        for (int k4 = 0; k4 < H_SIZE / 4; k4++) {
            float4 h0 = *(const float4*)&h_s[0][k4 * 4];
            float4 h1 = *(const float4*)&h_s[1][k4 * 4];
            a0 = fmaf(h0.x, w[4 * k4 + 0], a0);
            a1 = fmaf(h0.y, w[4 * k4 + 1], a1);
            a2 = fmaf(h0.z, w[4 * k4 + 2], a2);
            a3 = fmaf(h0.w, w[4 * k4 + 3], a3);
            d0 = fmaf(h1.x, w[4 * k4 + 0], d0);
            d1 = fmaf(h1.y, w[4 * k4 + 1], d1);
            d2 = fmaf(h1.z, w[4 * k4 + 2], d2);
            d3 = fmaf(h1.w, w[4 * k4 + 3], d3);
        }
        float acc0 = (a0 + a1) + (a2 + a3);
        float acc1 = (d0 + d1) + (d2 + d3);

        float z1r = 0.0f;
        if (g == 0) {
            r_s[0][j] = sigmoidf_(x0 + acc0);
            r_s[1][j] = sigmoidf_(x1 + acc1);
        } else if (g == 1) {
            z0_s[j] = sigmoidf_(x0 + acc0);
            z1r     = sigmoidf_(x1 + acc1);
        } else {
            a1_s[j]  = acc1;
            xn1_s[j] = x1;
        }
        __syncthreads();   // r, z0, a1, xn1 ready

        if (g == 2) {
            float h0o = h_s[0][j];
            float n0  = tanhf_(x0 + r_s[0][j] * (acc0 + bhn_j));
            float z0  = z0_s[j];
            float hn0 = (1.0f - z0) * n0 + z0 * h0o;
            h_s[0][j] = hn0;
            g_hs[((size_t)t * B_SIZE + b0) * H_SIZE + j] = hn0;
        } else if (g == 1) {
            float h1o = h_s[1][j];
            float n1  = tanhf_(xn1_s[j] + r_s[1][j] * (a1_s[j] + bhn_j));
            float hn1 = (1.0f - z1r) * n1 + z1r * h1o;
            h_s[1][j] = hn1;
            g_hs[((size_t)t * B_SIZE + b0 + 1) * H_SIZE + j] = hn1;
        }
        __syncthreads();   // h_new ready for next step's dot

        x0 = nx0;
        x1 = nx1;
    }
}

// ============================================================================
// Phase 3: classifier out[o] = sigmoid(dot(hs[o,:], Wc) + bc), o = t*B + b.
// Warp per output; memory-bound (268 MB streamed).
// ============================================================================
__global__ __launch_bounds__(256) void cls_kernel(
    const float* __restrict__ Wc, const float* __restrict__ bc,
    float* __restrict__ out)
{
    const int lane = threadIdx.x & 31;
    const size_t o = (size_t)blockIdx.x * 8 + (threadIdx.x >> 5);

    float4 h4 = *(const float4*)&g_hs[o * H_SIZE + lane * 4];
    float4 w4 = *(const float4*)&Wc[lane * 4];
    float v = fmaf(h4.x, w4.x, fmaf(h4.y, w4.y, fmaf(h4.z, w4.z, h4.w * w4.w)));
    #pragma unroll
    for (int off = 16; off > 0; off >>= 1)
        v += __shfl_down_sync(0xffffffffu, v, off);
    if (lane == 0) out[o] = sigmoidf_(v + bc[0]);
}

// ============================================================================
extern "C" void kernel_launch(void* const* d_in, const int* in_sizes, int n_in,
                              void* d_out, int out_size)
{
    const float* x    = (const float*)d_in[0];
    const float* Wir  = (const float*)d_in[1];
    const float* Wiz  = (const float*)d_in[2];
    const float* Win  = (const float*)d_in[3];
    const float* bir  = (const float*)d_in[4];
    const float* biz  = (const float*)d_in[5];
    const float* bin_ = (const float*)d_in[6];
    const float* Whr  = (const float*)d_in[7];
    const float* Whz  = (const float*)d_in[8];
    const float* Whn  = (const float*)d_in[9];
    const float* bhn  = (const float*)d_in[10];
    const float* Wc   = (const float*)d_in[11];
    const float* bc   = (const float*)d_in[12];
    float* out = (float*)d_out;

    // Phase 1: persistent input projections.
    xproj_kernel<<<3 * XP_BLOCKS_PER_GATE, 128>>>(x, Wir, Wiz, Win, bir, biz, bin_);

    // Phase 2: sequential recurrence, batch-parallel across 128 blocks.
    gru_kernel<<<B_SIZE / 2, 384>>>(Whr, Whz, Whn, bhn);

    // Phase 3: classifier over all T*B hidden states.
    cls_kernel<<<(T_STEPS * B_SIZE) / 8, 256>>>(Wc, bc, out);
}

// round 12
// speedup vs baseline: 1.0308x; 1.0308x over previous
#include <cuda_runtime.h>
#include <cstdint>
#include <cstddef>

#define T_STEPS 2048
#define B_SIZE  256
#define I_SIZE  64
#define H_SIZE  128

// Scratch: input projections x@Wi + bi, layout [T][B][3*H] (805 MB)
__device__ float g_xproj[(size_t)T_STEPS * B_SIZE * 3 * H_SIZE];
// Scratch: hidden states hs [T][B][H] (268 MB) for deferred classifier
__device__ float g_hs[(size_t)T_STEPS * B_SIZE * H_SIZE];

__device__ __forceinline__ float sigmoidf_(float x) {
    return 1.0f / (1.0f + __expf(-x));
}
__device__ __forceinline__ float tanhf_(float x) {
    return 1.0f - 2.0f / (1.0f + __expf(2.0f * x));
}

// ---- packed f32x2 helpers (Blackwell FFMA2) --------------------------------
__device__ __forceinline__ unsigned long long fma2_(unsigned long long a,
                                                    unsigned long long b,
                                                    unsigned long long c) {
    unsigned long long d;
    asm("fma.rn.f32x2 %0, %1, %2, %3;" : "=l"(d) : "l"(a), "l"(b), "l"(c));
    return d;
}
__device__ __forceinline__ unsigned long long dup2_(float x) {
    unsigned long long d;
    asm("mov.b64 %0, {%1, %1};" : "=l"(d) : "f"(x));
    return d;
}
__device__ __forceinline__ unsigned long long pack2_(float a, float b) {
    unsigned long long d;
    asm("mov.b64 %0, {%1, %2};" : "=l"(d) : "f"(a), "f"(b));
    return d;
}
__device__ __forceinline__ float2 unpack2_(unsigned long long v) {
    float2 r;
    asm("mov.b64 {%0, %1}, %2;" : "=f"(r.x), "=f"(r.y) : "l"(v));
    return r;
}

// ============================================================================
// Phase 1: xproj (exact R10 kernel — best measured: 615 us).
// Block tile = 64 rows x 128 cols (one gate), 128 threads, 4x16 register tile
// packed f32x2 over cols, XOR-swizzled transposed x tile. SMEM 48KB.
// ============================================================================
#define XS_IDX(i, row) ((i) * 64 + ((row) ^ ((i) & 60)))

__global__ __launch_bounds__(128, 3) void xproj_kernel(
    const float* __restrict__ x,
    const float* __restrict__ Wir, const float* __restrict__ Wiz, const float* __restrict__ Win,
    const float* __restrict__ bir, const float* __restrict__ biz, const float* __restrict__ bin_)
{
    __shared__ __align__(16) float xs[I_SIZE * 64];       // 16384 B
    __shared__ __align__(16) float ws[I_SIZE * H_SIZE];   // 32768 B

    const int g = blockIdx.y;
    const float* __restrict__ W    = (g == 0) ? Wir : (g == 1) ? Wiz : Win;
    const float* __restrict__ bias = (g == 0) ? bir : (g == 1) ? biz : bin_;

    const int tid = threadIdx.x;
    const size_t r_base = (size_t)blockIdx.x * 64;

    const float4* __restrict__ xg4 = (const float4*)(x + r_base * I_SIZE);
    #pragma unroll
    for (int s = 0; s < 8; s++) {
        int idx4 = tid + 128 * s;            // 0..1023 float4s
        float4 v = xg4[idx4];
        int row = idx4 >> 4;
        int i0  = (idx4 & 15) * 4;
        xs[XS_IDX(i0 + 0, row)] = v.x;
        xs[XS_IDX(i0 + 1, row)] = v.y;
        xs[XS_IDX(i0 + 2, row)] = v.z;
        xs[XS_IDX(i0 + 3, row)] = v.w;
    }
    const float4* __restrict__ Wg4 = (const float4*)W;
    #pragma unroll
    for (int s = 0; s < 16; s++) {
        int idx4 = tid + 128 * s;
        ((float4*)ws)[idx4] = Wg4[idx4];
    }
    __syncthreads();

    const int tr = tid & 15;
    const int tc = tid >> 4;
    const int r0 = tr * 4;
    const int c0 = tc * 16;

    unsigned long long accp[4][8];
    #pragma unroll
    for (int r = 0; r < 4; r++)
        #pragma unroll
        for (int c = 0; c < 8; c++)
            accp[r][c] = 0ull;

    #pragma unroll 4
    for (int k = 0; k < I_SIZE; k++) {
        float4 xa = *(const float4*)&xs[XS_IDX(k, r0)];
        const ulonglong2* wr = (const ulonglong2*)&ws[k * H_SIZE + c0];
        ulonglong2 wq0 = wr[0], wq1 = wr[1], wq2 = wr[2], wq3 = wr[3];
        unsigned long long wp[8] = {wq0.x, wq0.y, wq1.x, wq1.y,
                                    wq2.x, wq2.y, wq3.x, wq3.y};
        unsigned long long xd[4] = {dup2_(xa.x), dup2_(xa.y), dup2_(xa.z), dup2_(xa.w)};
        #pragma unroll
        for (int r = 0; r < 4; r++)
            #pragma unroll
            for (int c = 0; c < 8; c++)
                accp[r][c] = fma2_(xd[r], wp[c], accp[r][c]);
    }

    const float4* __restrict__ bp = (const float4*)(bias + c0);
    float4 b0 = bp[0], b1 = bp[1], b2 = bp[2], b3 = bp[3];
    float bv[16] = {b0.x, b0.y, b0.z, b0.w, b1.x, b1.y, b1.z, b1.w,
                    b2.x, b2.y, b2.z, b2.w, b3.x, b3.y, b3.z, b3.w};

    #pragma unroll
    for (int r = 0; r < 4; r++) {
        size_t row = r_base + (size_t)(r0 + r);
        float* op = g_xproj + row * (3 * H_SIZE) + g * H_SIZE + c0;
        #pragma unroll
        for (int q = 0; q < 4; q++) {
            float2 pa = unpack2_(accp[r][2 * q + 0]);
            float2 pb = unpack2_(accp[r][2 * q + 1]);
            float4 o;
            o.x = pa.x + bv[4 * q + 0];
            o.y = pa.y + bv[4 * q + 1];
            o.z = pb.x + bv[4 * q + 2];
            o.w = pb.y + bv[4 * q + 3];
            *(float4*)(op + 4 * q) = o;
        }
    }
}

// ============================================================================
// Phase 2: persistent per-batch GRU recurrence.
// R10 structure (parallel epilogue, x prefetch, deferred classifier) with the
// dot rewritten as packed FFMA2: w column as 64 f32x2 pairs (128 regs),
// h rows read as broadcast ulonglong2, 128 fma2/thread/step in 8 chains.
// ============================================================================
__global__ __launch_bounds__(384, 1) void gru_kernel(
    const float* __restrict__ Whr, const float* __restrict__ Whz, const float* __restrict__ Whn,
    const float* __restrict__ bhn)
{
    __shared__ __align__(16) float h_s[2][H_SIZE];
    __shared__ float r_s[2][H_SIZE];
    __shared__ float z0_s[H_SIZE];     // z row 0 (gate-1 keeps z1 in reg)
    __shared__ float a1_s[H_SIZE];     // n-dot row 1 (gate-2 keeps acc0)
    __shared__ float xn1_s[H_SIZE];    // xn row 1

    const int tid = threadIdx.x;
    const int g   = tid >> 7;       // 0=r, 1=z, 2=n
    const int j   = tid & 127;
    const int b0  = blockIdx.x * 2;

    const float* __restrict__ Wh = (g == 0) ? Whr : (g == 1) ? Whz : Whn;

    // Register-resident weight column packed over k pairs: w2[m]=(Wh[2m][j],Wh[2m+1][j])
    unsigned long long w2[H_SIZE / 2];
    #pragma unroll
    for (int m = 0; m < H_SIZE / 2; m++)
        w2[m] = pack2_(Wh[(2 * m) * H_SIZE + j], Wh[(2 * m + 1) * H_SIZE + j]);

    const float bhn_j = bhn[j];

    if (tid < 2 * H_SIZE) ((float*)h_s)[tid] = 0.0f;   // h0 = 0
    __syncthreads();

    const float* __restrict__ xp = g_xproj + (size_t)b0 * (3 * H_SIZE) + g * H_SIZE + j;
    const size_t step_stride = (size_t)B_SIZE * 3 * H_SIZE;

    const ulonglong2* __restrict__ h0q = (const ulonglong2*)h_s[0];
    const ulonglong2* __restrict__ h1q = (const ulonglong2*)h_s[1];

    float x0 = xp[0];
    float x1 = xp[3 * H_SIZE];

    for (int t = 0; t < T_STEPS; t++) {
        float nx0 = 0.0f, nx1 = 0.0f;
        if (t + 1 < T_STEPS) {
            const float* xq = xp + (size_t)(t + 1) * step_stride;
            nx0 = xq[0];
            nx1 = xq[3 * H_SIZE];
        }

        // acc[row] = sum_k h[row][k] * Wh[k][j] — packed over k.
        // 32 broadcast LDS.128 per row, 64 fma2 per row, 4 chains per row.
        unsigned long long p00 = 0ull, p01 = 0ull, p02 = 0ull, p03 = 0ull;
        unsigned long long p10 = 0ull, p11 = 0ull, p12 = 0ull, p13 = 0ull;
        #pragma unroll
        for (int m = 0; m < 16; m++) {       // two ulonglong2 per row per iter
            ulonglong2 va0 = h0q[2 * m];
            ulonglong2 vb0 = h0q[2 * m + 1];
            ulonglong2 va1 = h1q[2 * m];
            ulonglong2 vb1 = h1q[2 * m + 1];
            p00 = fma2_(va0.x, w2[4 * m + 0], p00);
            p01 = fma2_(va0.y, w2[4 * m + 1], p01);
            p02 = fma2_(vb0.x, w2[4 * m + 2], p02);
            p03 = fma2_(vb0.y, w2[4 * m + 3], p03);
            p10 = fma2_(va1.x, w2[4 * m + 0], p10);
            p11 = fma2_(va1.y, w2[4 * m + 1], p11);
            p12 = fma2_(vb1.x, w2[4 * m + 2], p12);
            p13 = fma2_(vb1.y, w2[4 * m + 3], p13);
        }
        float2 u0a = unpack2_(p00), u0b = unpack2_(p01);
        float2 u0c = unpack2_(p02), u0d = unpack2_(p03);
        float2 u1a = unpack2_(p10), u1b = unpack2_(p11);
        float2 u1c = unpack2_(p12), u1d = unpack2_(p13);
        float acc0 = ((u0a.x + u0a.y) + (u0b.x + u0b.y))
                   + ((u0c.x + u0c.y) + (u0d.x + u0d.y));
        float acc1 = ((u1a.x + u1a.y) + (u1b.x + u1b.y))
                   + ((u1c.x + u1c.y) + (u1d.x + u1d.y));

        float z1r = 0.0f;
        if (g == 0) {
            r_s[0][j] = sigmoidf_(x0 + acc0);
            r_s[1][j] = sigmoidf_(x1 + acc1);
        } else if (g == 1) {
            z0_s[j] = sigmoidf_(x0 + acc0);
            z1r     = sigmoidf_(x1 + acc1);
        } else {
            a1_s[j]  = acc1;
            xn1_s[j] = x1;
        }
        __syncthreads();   // r, z0, a1, xn1 ready

        if (g == 2) {
            float h0o = h_s[0][j];
            float n0  = tanhf_(x0 + r_s[0][j] * (acc0 + bhn_j));
            float z0  = z0_s[j];
            float hn0 = (1.0f - z0) * n0 + z0 * h0o;
            h_s[0][j] = hn0;
            g_hs[((size_t)t * B_SIZE + b0) * H_SIZE + j] = hn0;
        } else if (g == 1) {
            float h1o = h_s[1][j];
            float n1  = tanhf_(xn1_s[j] + r_s[1][j] * (a1_s[j] + bhn_j));
            float hn1 = (1.0f - z1r) * n1 + z1r * h1o;
            h_s[1][j] = hn1;
            g_hs[((size_t)t * B_SIZE + b0 + 1) * H_SIZE + j] = hn1;
        }
        __syncthreads();   // h_new ready for next step's dot

        x0 = nx0;
        x1 = nx1;
    }
}

// ============================================================================
// Phase 3: classifier out[o] = sigmoid(dot(hs[o,:], Wc) + bc).
// Warp per output; memory-bound (268 MB streamed).
// ============================================================================
__global__ __launch_bounds__(256) void cls_kernel(
    const float* __restrict__ Wc, const float* __restrict__ bc,
    float* __restrict__ out)
{
    const int lane = threadIdx.x & 31;
    const size_t o = (size_t)blockIdx.x * 8 + (threadIdx.x >> 5);

    float4 h4 = *(const float4*)&g_hs[o * H_SIZE + lane * 4];
    float4 w4 = *(const float4*)&Wc[lane * 4];
    float v = fmaf(h4.x, w4.x, fmaf(h4.y, w4.y, fmaf(h4.z, w4.z, h4.w * w4.w)));
    #pragma unroll
    for (int off = 16; off > 0; off >>= 1)
        v += __shfl_down_sync(0xffffffffu, v, off);
    if (lane == 0) out[o] = sigmoidf_(v + bc[0]);
}

// ============================================================================
extern "C" void kernel_launch(void* const* d_in, const int* in_sizes, int n_in,
                              void* d_out, int out_size)
{
    const float* x    = (const float*)d_in[0];
    const float* Wir  = (const float*)d_in[1];
    const float* Wiz  = (const float*)d_in[2];
    const float* Win  = (const float*)d_in[3];
    const float* bir  = (const float*)d_in[4];
    const float* biz  = (const float*)d_in[5];
    const float* bin_ = (const float*)d_in[6];
    const float* Whr  = (const float*)d_in[7];
    const float* Whz  = (const float*)d_in[8];
    const float* Whn  = (const float*)d_in[9];
    const float* bhn  = (const float*)d_in[10];
    const float* Wc   = (const float*)d_in[11];
    const float* bc   = (const float*)d_in[12];
    float* out = (float*)d_out;

    // Phase 1: input projections (R10 version).
    dim3 grid1((T_STEPS * B_SIZE) / 64, 3);
    xproj_kernel<<<grid1, 128>>>(x, Wir, Wiz, Win, bir, biz, bin_);

    // Phase 2: sequential recurrence, batch-parallel across 128 blocks.
    gru_kernel<<<B_SIZE / 2, 384>>>(Whr, Whz, Whn, bhn);

    // Phase 3: classifier over all T*B hidden states.
    cls_kernel<<<(T_STEPS * B_SIZE) / 8, 256>>>(Wc, bc, out);
}